// round 12
// baseline (speedup 1.0000x reference)
#include <cuda_runtime.h>
#include <math.h>

#define IMH 384
#define IMW 384
#define TH 48
#define TW 48
#define PAD 24
#define PIMH (IMH + 2*PAD)     // 432
#define PIMW (IMW + 2*PAD)     // 432
#define NB 16
#define MAXC (TH*TW)           // 2304

#define TPB 256                // 1 pixel per thread, 8 warps per CTA
#define TILE_W 16
#define TILE_H 16
#define IMT_STRIDE 72          // bytes per imtile row (18 words; bank-spread)

// ---- scratch (static device globals; no allocation allowed) ----
__device__ __align__(16) unsigned char g_imb[2 * PIMH * PIMW];  // padded binned image, 16 = OOB
__device__ __align__(16) unsigned char g_tb[2 * TH * TW];       // binned template
__device__ unsigned      g_mmu[8];                // [im|t][b][min,max] as monotone uint keys

// monotone float<->uint encoding (order-preserving for ALL floats)
__device__ __forceinline__ unsigned f2key(float f) {
    unsigned b = __float_as_uint(f);
    return (b & 0x80000000u) ? ~b : (b | 0x80000000u);
}
__device__ __forceinline__ float key2f(unsigned k) {
    unsigned b = (k & 0x80000000u) ? (k & 0x7FFFFFFFu) : ~k;
    return __uint_as_float(b);
}

// ---------------- init sentinels --------------------------------------------
__global__ void k_init() {
    if (threadIdx.x < 8)
        g_mmu[threadIdx.x] = (threadIdx.x & 1) ? 0u : 0xFFFFFFFFu;  // even=min, odd=max
}

// ---------------- parallel min/max reduction ---------------------------------
__global__ void k_red(const float* __restrict__ im, const float* __restrict__ tp) {
    int b = blockIdx.y;
    int which = (blockIdx.x == 73) ? 1 : 0;
    float mn = 3.0e38f, mx = -3.0e38f;
    if (which == 0) {
        const float4* src = (const float4*)(im + b * IMH * IMW);
        int base = blockIdx.x * 512;
        int end  = min(base + 512, (IMH * IMW) / 4);
        for (int i = base + threadIdx.x; i < end; i += blockDim.x) {
            float4 v = src[i];
            mn = fminf(fminf(fminf(mn, v.x), v.y), fminf(v.z, v.w));
            mx = fmaxf(fmaxf(fmaxf(mx, v.x), v.y), fmaxf(v.z, v.w));
        }
    } else {
        const float4* src = (const float4*)(tp + b * TH * TW);
        for (int i = threadIdx.x; i < (TH * TW) / 4; i += blockDim.x) {
            float4 v = src[i];
            mn = fminf(fminf(fminf(mn, v.x), v.y), fminf(v.z, v.w));
            mx = fmaxf(fmaxf(fmaxf(mx, v.x), v.y), fmaxf(v.z, v.w));
        }
    }
    for (int o = 16; o; o >>= 1) {
        mn = fminf(mn, __shfl_xor_sync(0xffffffffu, mn, o));
        mx = fmaxf(mx, __shfl_xor_sync(0xffffffffu, mx, o));
    }
    __shared__ float smn[8], smx[8];
    int lane = threadIdx.x & 31, warp = threadIdx.x >> 5;
    if (lane == 0) { smn[warp] = mn; smx[warp] = mx; }
    __syncthreads();
    if (threadIdx.x == 0) {
        int nw = blockDim.x >> 5;
        for (int w = 1; w < nw; w++) { mn = fminf(mn, smn[w]); mx = fmaxf(mx, smx[w]); }
        atomicMin(&g_mmu[which * 4 + b * 2 + 0], f2key(mn));
        atomicMax(&g_mmu[which * 4 + b * 2 + 1], f2key(mx));
    }
}

// ------------- binning, fused: blocks 0..728 = padded image, block 729 = template
__global__ void k_bin(const float* __restrict__ im, const float* __restrict__ tp) {
    int b = blockIdx.y;
    if (blockIdx.x < (PIMH * PIMW) / 256) {
        int idx = blockIdx.x * 256 + threadIdx.x;
        int py = idx / PIMW, px = idx - py * PIMW;
        unsigned char q = 16;  // OOB sentinel
        if (py >= PAD && py < PAD + IMH && px >= PAD && px < PAD + IMW) {
            float mn = key2f(g_mmu[b * 2 + 0]), mx = key2f(g_mmu[b * 2 + 1]);
            float v = im[b * IMH * IMW + (py - PAD) * IMW + (px - PAD)];
            float r = (v - mn) / (mx - mn);
            q = (unsigned char)(int)floorf(r * 15.0f);
        }
        g_imb[b * PIMH * PIMW + idx] = q;
    } else {
        float mn = key2f(g_mmu[4 + b * 2 + 0]), mx = key2f(g_mmu[4 + b * 2 + 1]);
        for (int i = threadIdx.x; i < TH * TW; i += 256) {
            float v = tp[b * TH * TW + i];
            float r = (v - mn) / (mx - mn);
            g_tb[b * TH * TW + i] = (unsigned char)(int)floorf(r * 15.0f);
        }
    }
}

// ---------------- main kernel ------------------------------------------------
// Dynamic smem layout (bytes):
//   [0)       hist: u8 [272 bins][256 B slab]  (1 px/thread) = 69632
//   [69632)   imtile: u8 [63 rows][72 stride]                = 4536 (+8 pad)
//   [74176)   ttile:  u8 [48*48]                             = 2304
// total = 76480  ->  3 CTAs x 76480 = 229440 <= 233472 (228KB)
#define SM_IMT    69632
#define SM_TT     74176
#define SM_TOTAL  76480

__device__ __forceinline__ float xlnx(int c) {
    float f = (float)c;
    return f * __logf(fmaxf(f, 1.0f));   // exact 0 at c=0 and c=1
}

#define GETB(arr, j) ((arr[(j) >> 2] >> (((j) & 3) * 8)) & 0xFFu)

__device__ __forceinline__ int mad32(int a, int b, int c) {
    int r;
    asm("mad.lo.s32 %0, %1, %2, %3;" : "=r"(r) : "r"(a), "r"(b), "r"(c));
    return r;   // steer address math onto the (idle) fma pipe as IMAD
}

__global__ void __launch_bounds__(TPB, 3) k_main(float* __restrict__ out) {
    extern __shared__ unsigned char smem[];
    unsigned char*  hist   = smem;
    unsigned char*  imtile = smem + SM_IMT;
    unsigned char*  ttile  = smem + SM_TT;

    const int tid = threadIdx.x;
    const int b  = blockIdx.z;
    const int x0 = blockIdx.x * TILE_W;
    const int y0 = blockIdx.y * TILE_H;

    // zero histogram (69632 B = 4352 uint4; 17 per thread)
    {
        uint4* h16 = (uint4*)smem;
        uint4 z = make_uint4(0u, 0u, 0u, 0u);
        #pragma unroll
        for (int k = 0; k < 17; k++) h16[k * TPB + tid] = z;
    }
    // template tile: 2304 B = 144 uint4
    {
        const uint4* src = (const uint4*)(g_tb + b * TH * TW);
        uint4* dst = (uint4*)ttile;
        if (tid < 144) dst[tid] = src[tid];
    }
    // image tile: 63 rows x 16 words each, row stride 72 B
    {
        const unsigned* src32 = (const unsigned*)g_imb;
        for (int k = tid; k < 63 * 16; k += TPB) {
            int r = k >> 4, c = k & 15;
            unsigned v = src32[(b * PIMH * PIMW + (y0 + r) * PIMW + x0) / 4 + c];
            *(unsigned*)(imtile + r * IMT_STRIDE + c * 4) = v;
        }
    }
    __syncthreads();

    const int cx = tid & 15;       // pixel column 0..15
    const int ry = tid >> 4;       // pixel row 0..15
    const int lane = tid & 31;
    const int warp = tid >> 5;     // 0..7
    // bijective slot for 256 threads; word-in-slab = lane + (warp>>2)*32
    //  -> bank = lane, conflict-free for every warp, every bin
    const int hbase = (warp >> 2) * 128 + lane * 4 + (warp & 3);

    const int off0 = ry * IMT_STRIDE + cx;
    const int sh = (off0 & 3) * 8;
    const unsigned* im32 = (const unsigned*)imtile;
    const unsigned* tt32 = (const unsigned*)ttile;

    #pragma unroll 1
    for (int i = 0; i < TH; i++) {
        // preload this thread's 48-byte image span, realign in place
        const int base = (off0 + i * IMT_STRIDE) >> 2;
        unsigned w[13];
        #pragma unroll
        for (int q = 0; q < 13; q++) w[q] = im32[base + q];
        #pragma unroll
        for (int q = 0; q < 12; q++) w[q] = __funnelshift_r(w[q], w[q + 1], sh);
        unsigned t[12];
        #pragma unroll
        for (int q = 0; q < 12; q++) t[q] = tt32[i * 12 + q];

        #pragma unroll
        for (int j = 0; j < TW; j++) {
            int m  = (int)GETB(w, j);
            int tb = (int)GETB(t, j);
            int a  = mad32(m, 4096, mad32(tb, 256, hbase));
            unsigned char c = hist[a];
            hist[a] = (unsigned char)(c + 1);
        }
    }
    __syncthreads();

    // ---- epilogue: KL from counts via MI identity (MUFU c*ln c) ----
    {
        const unsigned char* h = hist + hbase;
        float Sxy = 0.0f, Sx = 0.0f;
        int N = 0;
        int cyAcc[16];
        #pragma unroll
        for (int by = 0; by < 16; by++) cyAcc[by] = 0;
        #pragma unroll
        for (int bx = 0; bx < 16; bx++) {   // bx==16 (OOB row) excluded
            int cxs = 0;
            #pragma unroll
            for (int by = 0; by < 16; by++) {
                int c = h[((bx << 4) + by) * 256];
                cxs += c;
                cyAcc[by] += c;
                Sxy += xlnx(c);
            }
            Sx += xlnx(cxs);
            N += cxs;
        }
        float Sy = 0.0f;
        #pragma unroll
        for (int by = 0; by < 16; by++) Sy += xlnx(cyAcc[by]);
        float kl = (Sxy - Sx - Sy + xlnx(N)) / (float)N;
        out[b * IMH * IMW + (y0 + ry) * IMW + x0 + cx] = kl;
    }
}

// ---------------- launch -----------------------------------------------------
extern "C" void kernel_launch(void* const* d_in, const int* in_sizes, int n_in,
                              void* d_out, int out_size) {
    const float* im = (const float*)d_in[0];
    const float* tp = (const float*)d_in[1];
    if (n_in >= 2 && in_sizes[0] < in_sizes[1]) {  // defensive: im is the big one
        const float* t = im; im = tp; tp = t;
    }
    float* out = (float*)d_out;

    cudaFuncSetAttribute(k_main, cudaFuncAttributeMaxDynamicSharedMemorySize, SM_TOTAL);
    // Max smem carveout so THREE CTAs fit per SM.
    cudaFuncSetAttribute(k_main, cudaFuncAttributePreferredSharedMemoryCarveout, 100);

    k_init<<<1, 32>>>();
    k_red<<<dim3(74, 2), 256>>>(im, tp);
    k_bin<<<dim3((PIMH * PIMW) / 256 + 1, 2), 256>>>(im, tp);
    k_main<<<dim3(IMW / TILE_W, IMH / TILE_H, 2), TPB, SM_TOTAL>>>(out);
}

// round 13
// speedup vs baseline: 1.0917x; 1.0917x over previous
#include <cuda_runtime.h>
#include <math.h>

#define IMH 384
#define IMW 384
#define TH 48
#define TW 48
#define PAD 24
#define PIMH (IMH + 2*PAD)     // 432
#define PIMW (IMW + 2*PAD)     // 432
#define NB 16
#define MAXC (TH*TW)           // 2304

#define TPB 256                // 1 pixel per thread, 8 warps per CTA
#define TILE_W 16
#define TILE_H 16
#define IMT_STRIDE 72          // bytes per imtile row (18 words; bank-spread)

// ---- scratch (static device globals; no allocation allowed) ----
__device__ __align__(16) unsigned char g_imb[2 * PIMH * PIMW];  // padded binned image, 16 = OOB
__device__ __align__(16) unsigned char g_tb[2 * TH * TW];       // binned template
__device__ unsigned      g_mmu[8];                // [im|t][b][min,max] as monotone uint keys

// monotone float<->uint encoding (order-preserving for ALL floats)
__device__ __forceinline__ unsigned f2key(float f) {
    unsigned b = __float_as_uint(f);
    return (b & 0x80000000u) ? ~b : (b | 0x80000000u);
}
__device__ __forceinline__ float key2f(unsigned k) {
    unsigned b = (k & 0x80000000u) ? (k & 0x7FFFFFFFu) : ~k;
    return __uint_as_float(b);
}

// ---------------- init sentinels --------------------------------------------
__global__ void k_init() {
    if (threadIdx.x < 8)
        g_mmu[threadIdx.x] = (threadIdx.x & 1) ? 0u : 0xFFFFFFFFu;  // even=min, odd=max
}

// ---------------- parallel min/max reduction ---------------------------------
__global__ void k_red(const float* __restrict__ im, const float* __restrict__ tp) {
    int b = blockIdx.y;
    int which = (blockIdx.x == 73) ? 1 : 0;
    float mn = 3.0e38f, mx = -3.0e38f;
    if (which == 0) {
        const float4* src = (const float4*)(im + b * IMH * IMW);
        int base = blockIdx.x * 512;
        int end  = min(base + 512, (IMH * IMW) / 4);
        for (int i = base + threadIdx.x; i < end; i += blockDim.x) {
            float4 v = src[i];
            mn = fminf(fminf(fminf(mn, v.x), v.y), fminf(v.z, v.w));
            mx = fmaxf(fmaxf(fmaxf(mx, v.x), v.y), fmaxf(v.z, v.w));
        }
    } else {
        const float4* src = (const float4*)(tp + b * TH * TW);
        for (int i = threadIdx.x; i < (TH * TW) / 4; i += blockDim.x) {
            float4 v = src[i];
            mn = fminf(fminf(fminf(mn, v.x), v.y), fminf(v.z, v.w));
            mx = fmaxf(fmaxf(fmaxf(mx, v.x), v.y), fmaxf(v.z, v.w));
        }
    }
    for (int o = 16; o; o >>= 1) {
        mn = fminf(mn, __shfl_xor_sync(0xffffffffu, mn, o));
        mx = fmaxf(mx, __shfl_xor_sync(0xffffffffu, mx, o));
    }
    __shared__ float smn[8], smx[8];
    int lane = threadIdx.x & 31, warp = threadIdx.x >> 5;
    if (lane == 0) { smn[warp] = mn; smx[warp] = mx; }
    __syncthreads();
    if (threadIdx.x == 0) {
        int nw = blockDim.x >> 5;
        for (int w = 1; w < nw; w++) { mn = fminf(mn, smn[w]); mx = fmaxf(mx, smx[w]); }
        atomicMin(&g_mmu[which * 4 + b * 2 + 0], f2key(mn));
        atomicMax(&g_mmu[which * 4 + b * 2 + 1], f2key(mx));
    }
}

// ------------- binning, fused: blocks 0..728 = padded image, block 729 = template
__global__ void k_bin(const float* __restrict__ im, const float* __restrict__ tp) {
    int b = blockIdx.y;
    if (blockIdx.x < (PIMH * PIMW) / 256) {
        int idx = blockIdx.x * 256 + threadIdx.x;
        int py = idx / PIMW, px = idx - py * PIMW;
        unsigned char q = 16;  // OOB sentinel
        if (py >= PAD && py < PAD + IMH && px >= PAD && px < PAD + IMW) {
            float mn = key2f(g_mmu[b * 2 + 0]), mx = key2f(g_mmu[b * 2 + 1]);
            float v = im[b * IMH * IMW + (py - PAD) * IMW + (px - PAD)];
            float r = (v - mn) / (mx - mn);
            q = (unsigned char)(int)floorf(r * 15.0f);
        }
        g_imb[b * PIMH * PIMW + idx] = q;
    } else {
        float mn = key2f(g_mmu[4 + b * 2 + 0]), mx = key2f(g_mmu[4 + b * 2 + 1]);
        for (int i = threadIdx.x; i < TH * TW; i += 256) {
            float v = tp[b * TH * TW + i];
            float r = (v - mn) / (mx - mn);
            g_tb[b * TH * TW + i] = (unsigned char)(int)floorf(r * 15.0f);
        }
    }
}

// ---------------- main kernel ------------------------------------------------
// Dynamic smem layout (bytes):
//   [0)       hist: u8 [272 bins][256 B slab]  (1 px/thread) = 69632
//   [69632)   imtile: u8 [63 rows][72 stride]                = 4536 (+8 pad)
//   [74176)   ttile:  u8 [48*48]                             = 2304
// total = 76480  ->  3 CTAs x 76480 = 229440 <= 233472 (228KB)
#define SM_IMT    69632
#define SM_TT     74176
#define SM_TOTAL  76480

__device__ __forceinline__ float xlnx(int c) {
    float f = (float)c;
    return f * __logf(fmaxf(f, 1.0f));   // exact 0 at c=0 and c=1
}

// single-PRMT byte extract (selector is compile-time in the unrolled loop)
#define PRMTB(arr, j) __byte_perm((arr)[(j) >> 2], 0u, 0x4440u | (unsigned)((j) & 3))

__device__ __forceinline__ int mad32(int a, int b, int c) {
    int r;
    asm("mad.lo.s32 %0, %1, %2, %3;" : "=r"(r) : "r"(a), "r"(b), "r"(c));
    return r;   // IMAD on the fma pipe
}

__global__ void __launch_bounds__(TPB, 3) k_main(float* __restrict__ out) {
    extern __shared__ unsigned char smem[];
    unsigned char*  hist   = smem;
    unsigned char*  imtile = smem + SM_IMT;
    unsigned char*  ttile  = smem + SM_TT;

    const int tid = threadIdx.x;
    const int b  = blockIdx.z;
    const int x0 = blockIdx.x * TILE_W;
    const int y0 = blockIdx.y * TILE_H;

    // zero histogram (69632 B = 4352 uint4; 17 per thread)
    {
        uint4* h16 = (uint4*)smem;
        uint4 z = make_uint4(0u, 0u, 0u, 0u);
        #pragma unroll
        for (int k = 0; k < 17; k++) h16[k * TPB + tid] = z;
    }
    // template tile: 2304 B = 144 uint4
    {
        const uint4* src = (const uint4*)(g_tb + b * TH * TW);
        uint4* dst = (uint4*)ttile;
        if (tid < 144) dst[tid] = src[tid];
    }
    // image tile: 63 rows x 16 words each, row stride 72 B
    {
        const unsigned* src32 = (const unsigned*)g_imb;
        for (int k = tid; k < 63 * 16; k += TPB) {
            int r = k >> 4, c = k & 15;
            unsigned v = src32[(b * PIMH * PIMW + (y0 + r) * PIMW + x0) / 4 + c];
            *(unsigned*)(imtile + r * IMT_STRIDE + c * 4) = v;
        }
    }
    __syncthreads();

    const int cx = tid & 15;       // pixel column 0..15
    const int ry = tid >> 4;       // pixel row 0..15
    const int lane = tid & 31;
    const int warp = tid >> 5;     // 0..7
    // bijective slot for 256 threads; word-in-slab = lane + (warp>>2)*32
    //  -> bank = lane, conflict-free for every warp, every bin
    const int hbase = (warp >> 2) * 128 + lane * 4 + (warp & 3);

    const int off0 = ry * IMT_STRIDE + cx;
    const int sh = (off0 & 3) * 8;
    const unsigned* im32 = (const unsigned*)imtile;
    const unsigned* tt32 = (const unsigned*)ttile;

    #pragma unroll 1
    for (int i = 0; i < TH; i++) {
        // preload this thread's 48-byte image span, realign in place
        const int base = (off0 + i * IMT_STRIDE) >> 2;
        unsigned w[13];
        #pragma unroll
        for (int q = 0; q < 13; q++) w[q] = im32[base + q];
        #pragma unroll
        for (int q = 0; q < 12; q++) w[q] = __funnelshift_r(w[q], w[q + 1], sh);
        unsigned t[12];
        #pragma unroll
        for (int q = 0; q < 12; q++) t[q] = tt32[i * 12 + q];

        #pragma unroll
        for (int j = 0; j < TW; j++) {
            int m  = (int)PRMTB(w, j);                 // 1 PRMT (alu)
            int tb = (int)PRMTB(t, j);                 // 1 PRMT (alu)
            int a  = mad32(m, 4096, mad32(tb, 256, hbase));  // 2 IMAD (fma)
            unsigned char c = hist[a];
            hist[a] = (unsigned char)(c + 1);
        }
    }
    __syncthreads();

    // ---- epilogue: KL from counts via MI identity (MUFU c*ln c) ----
    {
        const unsigned char* h = hist + hbase;
        float Sxy = 0.0f, Sx = 0.0f;
        int N = 0;
        int cyAcc[16];
        #pragma unroll
        for (int by = 0; by < 16; by++) cyAcc[by] = 0;
        #pragma unroll
        for (int bx = 0; bx < 16; bx++) {   // bx==16 (OOB row) excluded
            int cxs = 0;
            #pragma unroll
            for (int by = 0; by < 16; by++) {
                int c = h[((bx << 4) + by) * 256];
                cxs += c;
                cyAcc[by] += c;
                Sxy += xlnx(c);
            }
            Sx += xlnx(cxs);
            N += cxs;
        }
        float Sy = 0.0f;
        #pragma unroll
        for (int by = 0; by < 16; by++) Sy += xlnx(cyAcc[by]);
        float kl = (Sxy - Sx - Sy + xlnx(N)) / (float)N;
        out[b * IMH * IMW + (y0 + ry) * IMW + x0 + cx] = kl;
    }
}

// ---------------- launch -----------------------------------------------------
extern "C" void kernel_launch(void* const* d_in, const int* in_sizes, int n_in,
                              void* d_out, int out_size) {
    const float* im = (const float*)d_in[0];
    const float* tp = (const float*)d_in[1];
    if (n_in >= 2 && in_sizes[0] < in_sizes[1]) {  // defensive: im is the big one
        const float* t = im; im = tp; tp = t;
    }
    float* out = (float*)d_out;

    cudaFuncSetAttribute(k_main, cudaFuncAttributeMaxDynamicSharedMemorySize, SM_TOTAL);
    // Max smem carveout so THREE CTAs fit per SM.
    cudaFuncSetAttribute(k_main, cudaFuncAttributePreferredSharedMemoryCarveout, 100);

    k_init<<<1, 32>>>();
    k_red<<<dim3(74, 2), 256>>>(im, tp);
    k_bin<<<dim3((PIMH * PIMW) / 256 + 1, 2), 256>>>(im, tp);
    k_main<<<dim3(IMW / TILE_W, IMH / TILE_H, 2), TPB, SM_TOTAL>>>(out);
}

// round 15
// speedup vs baseline: 1.1474x; 1.0510x over previous
#include <cuda_runtime.h>
#include <math.h>

#define IMH 384
#define IMW 384
#define TH 48
#define TW 48
#define PAD 24
#define PIMH (IMH + 2*PAD)     // 432
#define PIMW (IMW + 2*PAD)     // 432
#define NB 16
#define MAXC (TH*TW)           // 2304

#define TPB 256                // 1 pixel per thread, 8 warps per CTA
#define TILE_W 16
#define TILE_H 16
#define IMT_STRIDE 72          // bytes per imtile row (18 words; bank-spread)

// ---- scratch (static device globals; no allocation allowed) ----
__device__ __align__(16) unsigned char g_imb[2 * PIMH * PIMW];  // padded binned image, 16 = OOB
__device__ __align__(16) unsigned char g_tb[2 * TH * TW];       // binned template
__device__ unsigned      g_mmu[8];                // [im|t][b][min,max] as monotone uint keys

// monotone float<->uint encoding (order-preserving for ALL floats)
__device__ __forceinline__ unsigned f2key(float f) {
    unsigned b = __float_as_uint(f);
    return (b & 0x80000000u) ? ~b : (b | 0x80000000u);
}
__device__ __forceinline__ float key2f(unsigned k) {
    unsigned b = (k & 0x80000000u) ? (k & 0x7FFFFFFFu) : ~k;
    return __uint_as_float(b);
}

// ---------------- init sentinels --------------------------------------------
__global__ void k_init() {
    if (threadIdx.x < 8)
        g_mmu[threadIdx.x] = (threadIdx.x & 1) ? 0u : 0xFFFFFFFFu;  // even=min, odd=max
}

// ---------------- parallel min/max reduction ---------------------------------
__global__ void k_red(const float* __restrict__ im, const float* __restrict__ tp) {
    int b = blockIdx.y;
    int which = (blockIdx.x == 73) ? 1 : 0;
    float mn = 3.0e38f, mx = -3.0e38f;
    if (which == 0) {
        const float4* src = (const float4*)(im + b * IMH * IMW);
        int base = blockIdx.x * 512;
        int end  = min(base + 512, (IMH * IMW) / 4);
        for (int i = base + threadIdx.x; i < end; i += blockDim.x) {
            float4 v = src[i];
            mn = fminf(fminf(fminf(mn, v.x), v.y), fminf(v.z, v.w));
            mx = fmaxf(fmaxf(fmaxf(mx, v.x), v.y), fmaxf(v.z, v.w));
        }
    } else {
        const float4* src = (const float4*)(tp + b * TH * TW);
        for (int i = threadIdx.x; i < (TH * TW) / 4; i += blockDim.x) {
            float4 v = src[i];
            mn = fminf(fminf(fminf(mn, v.x), v.y), fminf(v.z, v.w));
            mx = fmaxf(fmaxf(fmaxf(mx, v.x), v.y), fmaxf(v.z, v.w));
        }
    }
    for (int o = 16; o; o >>= 1) {
        mn = fminf(mn, __shfl_xor_sync(0xffffffffu, mn, o));
        mx = fmaxf(mx, __shfl_xor_sync(0xffffffffu, mx, o));
    }
    __shared__ float smn[8], smx[8];
    int lane = threadIdx.x & 31, warp = threadIdx.x >> 5;
    if (lane == 0) { smn[warp] = mn; smx[warp] = mx; }
    __syncthreads();
    if (threadIdx.x == 0) {
        int nw = blockDim.x >> 5;
        for (int w = 1; w < nw; w++) { mn = fminf(mn, smn[w]); mx = fmaxf(mx, smx[w]); }
        atomicMin(&g_mmu[which * 4 + b * 2 + 0], f2key(mn));
        atomicMax(&g_mmu[which * 4 + b * 2 + 1], f2key(mx));
    }
}

// ------------- binning, fused: blocks 0..728 = padded image, block 729 = template
__global__ void k_bin(const float* __restrict__ im, const float* __restrict__ tp) {
    int b = blockIdx.y;
    if (blockIdx.x < (PIMH * PIMW) / 256) {
        int idx = blockIdx.x * 256 + threadIdx.x;
        int py = idx / PIMW, px = idx - py * PIMW;
        unsigned char q = 16;  // OOB sentinel
        if (py >= PAD && py < PAD + IMH && px >= PAD && px < PAD + IMW) {
            float mn = key2f(g_mmu[b * 2 + 0]), mx = key2f(g_mmu[b * 2 + 1]);
            float v = im[b * IMH * IMW + (py - PAD) * IMW + (px - PAD)];
            float r = (v - mn) / (mx - mn);
            q = (unsigned char)(int)floorf(r * 15.0f);
        }
        g_imb[b * PIMH * PIMW + idx] = q;
    } else {
        float mn = key2f(g_mmu[4 + b * 2 + 0]), mx = key2f(g_mmu[4 + b * 2 + 1]);
        for (int i = threadIdx.x; i < TH * TW; i += 256) {
            float v = tp[b * TH * TW + i];
            float r = (v - mn) / (mx - mn);
            g_tb[b * TH * TW + i] = (unsigned char)(int)floorf(r * 15.0f);
        }
    }
}

// ---------------- main kernel ------------------------------------------------
// Dynamic smem layout (bytes):
//   [0)       hist: u8 [272 bins][256 B slab]  (1 px/thread) = 69632
//   [69632)   imtile: u8 [63 rows][72 stride]                = 4536 (+8 pad)
//   [74176)   ttile:  u8 [48*48]                             = 2304
// total = 76480  ->  3 CTAs x 76480 = 229440 <= 233472 (228KB)
#define SM_IMT    69632
#define SM_TT     74176
#define SM_TOTAL  76480

__device__ __forceinline__ float xlnx(int c) {
    float f = (float)c;
    return f * __logf(fmaxf(f, 1.0f));   // exact 0 at c=0 and c=1
}

// single-PRMT byte extract (selector is compile-time in the unrolled loop)
#define PRMTB(arr, j) __byte_perm((arr)[(j) >> 2], 0u, 0x4440u | (unsigned)((j) & 3))

__device__ __forceinline__ int mad32(int a, int b, int c) {
    int r;
    asm("mad.lo.s32 %0, %1, %2, %3;" : "=r"(r) : "r"(a), "r"(b), "r"(c));
    return r;
}

// M1/M2 arrive as runtime kernel arguments (always 4096 / 256). ptxas cannot
// const-prop param-bank values -> emits true 3-reg IMAD on the fma pipe
// instead of LEA/SHF on the (saturated) alu pipe.
__global__ void __launch_bounds__(TPB, 3) k_main(float* __restrict__ out, int M1, int M2) {
    extern __shared__ unsigned char smem[];
    unsigned char*  hist   = smem;
    unsigned char*  imtile = smem + SM_IMT;
    unsigned char*  ttile  = smem + SM_TT;

    const int tid = threadIdx.x;
    const int b  = blockIdx.z;
    const int x0 = blockIdx.x * TILE_W;
    const int y0 = blockIdx.y * TILE_H;

    // zero histogram (69632 B = 4352 uint4; 17 per thread)
    {
        uint4* h16 = (uint4*)smem;
        uint4 z = make_uint4(0u, 0u, 0u, 0u);
        #pragma unroll
        for (int k = 0; k < 17; k++) h16[k * TPB + tid] = z;
    }
    // template tile: 2304 B = 144 uint4
    {
        const uint4* src = (const uint4*)(g_tb + b * TH * TW);
        uint4* dst = (uint4*)ttile;
        if (tid < 144) dst[tid] = src[tid];
    }
    // image tile: 63 rows x 16 words each, row stride 72 B
    {
        const unsigned* src32 = (const unsigned*)g_imb;
        for (int k = tid; k < 63 * 16; k += TPB) {
            int r = k >> 4, c = k & 15;
            unsigned v = src32[(b * PIMH * PIMW + (y0 + r) * PIMW + x0) / 4 + c];
            *(unsigned*)(imtile + r * IMT_STRIDE + c * 4) = v;
        }
    }
    __syncthreads();

    const int cx = tid & 15;       // pixel column 0..15
    const int ry = tid >> 4;       // pixel row 0..15
    const int lane = tid & 31;
    const int warp = tid >> 5;     // 0..7
    // bijective slot for 256 threads; word-in-slab = lane + (warp>>2)*32
    //  -> bank = lane, conflict-free for every warp, every bin
    const int hbase = (warp >> 2) * 128 + lane * 4 + (warp & 3);

    const int off0 = ry * IMT_STRIDE + cx;
    const int sh = (off0 & 3) * 8;
    const unsigned* im32 = (const unsigned*)imtile;
    const unsigned* tt32 = (const unsigned*)ttile;

    #pragma unroll 1
    for (int i = 0; i < TH; i++) {
        // preload this thread's 48-byte image span, realign in place
        const int base = (off0 + i * IMT_STRIDE) >> 2;
        unsigned w[13];
        #pragma unroll
        for (int q = 0; q < 13; q++) w[q] = im32[base + q];
        #pragma unroll
        for (int q = 0; q < 12; q++) w[q] = __funnelshift_r(w[q], w[q + 1], sh);
        unsigned t[12];
        #pragma unroll
        for (int q = 0; q < 12; q++) t[q] = tt32[i * 12 + q];

        #pragma unroll
        for (int j = 0; j < TW; j++) {
            int m  = (int)PRMTB(w, j);                       // 1 PRMT (alu)
            int tb = (int)PRMTB(t, j);                       // 1 PRMT (alu)
            int a  = mad32(m, M1, mad32(tb, M2, hbase));     // 2 true IMAD (fma)
            unsigned char c = hist[a];
            hist[a] = (unsigned char)(c + 1);
        }
    }
    __syncthreads();

    // ---- epilogue: KL from counts via MI identity (MUFU c*ln c) ----
    {
        const unsigned char* h = hist + hbase;
        float Sxy = 0.0f, Sx = 0.0f;
        int N = 0;
        int cyAcc[16];
        #pragma unroll
        for (int by = 0; by < 16; by++) cyAcc[by] = 0;
        #pragma unroll
        for (int bx = 0; bx < 16; bx++) {   // bx==16 (OOB row) excluded
            int cxs = 0;
            #pragma unroll
            for (int by = 0; by < 16; by++) {
                int c = h[((bx << 4) + by) * 256];
                cxs += c;
                cyAcc[by] += c;
                Sxy += xlnx(c);
            }
            Sx += xlnx(cxs);
            N += cxs;
        }
        float Sy = 0.0f;
        #pragma unroll
        for (int by = 0; by < 16; by++) Sy += xlnx(cyAcc[by]);
        float kl = (Sxy - Sx - Sy + xlnx(N)) / (float)N;
        out[b * IMH * IMW + (y0 + ry) * IMW + x0 + cx] = kl;
    }
}

// ---------------- launch -----------------------------------------------------
extern "C" void kernel_launch(void* const* d_in, const int* in_sizes, int n_in,
                              void* d_out, int out_size) {
    const float* im = (const float*)d_in[0];
    const float* tp = (const float*)d_in[1];
    if (n_in >= 2 && in_sizes[0] < in_sizes[1]) {  // defensive: im is the big one
        const float* t = im; im = tp; tp = t;
    }
    float* out = (float*)d_out;

    cudaFuncSetAttribute(k_main, cudaFuncAttributeMaxDynamicSharedMemorySize, SM_TOTAL);
    // Max smem carveout so THREE CTAs fit per SM.
    cudaFuncSetAttribute(k_main, cudaFuncAttributePreferredSharedMemoryCarveout, 100);

    k_init<<<1, 32>>>();
    k_red<<<dim3(74, 2), 256>>>(im, tp);
    k_bin<<<dim3((PIMH * PIMW) / 256 + 1, 2), 256>>>(im, tp);
    k_main<<<dim3(IMW / TILE_W, IMH / TILE_H, 2), TPB, SM_TOTAL>>>(out, 4096, 256);
}